// round 5
// baseline (speedup 1.0000x reference)
#include <cuda_runtime.h>
#include <cstdint>

#define NN 100000
#define EE 1600000
#define INCH 128
#define HID 64
#define OUTC 40

// ---------------- scratch (device globals; no allocation allowed) ----------------
__device__ int   g_cnt[NN];
__device__ int   g_offs[NN + 1];
__device__ int   g_cursor[NN];
__device__ int   g_adj[EE];
__device__ float g_dinv[NN];
__device__ float g_xw[(size_t)NN * HID];   // x @ W1
__device__ float g_h1[(size_t)NN * HID];   // relu(agg1)
__device__ float g_h2[(size_t)NN * OUTC];  // h1 @ W2
__device__ int   g_bsum[128];
__device__ int   g_bscan[128];
__device__ int   g_is64;

// ---------------- edge dtype sniffing (int64 vs int32) ----------------
__global__ void detect_kernel(const void* ei) {
    const unsigned int* w = (const unsigned int*)ei;
    int is64 = 1;
    for (int i = 0; i < 64; i++) {
        if (w[2 * i + 1] != 0u) { is64 = 0; break; }
    }
    g_is64 = is64;
}

__device__ __forceinline__ int edge_row(const void* ei, int e, int is64) {
    if (is64) return (int)((const long long*)ei)[e];
    return ((const int*)ei)[e];
}
__device__ __forceinline__ int edge_col(const void* ei, int e, int is64) {
    if (is64) return (int)((const long long*)ei)[EE + e];
    return ((const int*)ei)[EE + e];
}

// ---------------- CSR build ----------------
__global__ void zero_cnt_kernel() {
    int i = blockIdx.x * blockDim.x + threadIdx.x;
    if (i < NN) g_cnt[i] = 0;
}

__global__ void hist_kernel(const void* __restrict__ ei) {
    int is64 = g_is64;
    for (int e = blockIdx.x * blockDim.x + threadIdx.x; e < EE; e += gridDim.x * blockDim.x) {
        int c = edge_col(ei, e, is64);
        atomicAdd(&g_cnt[c], 1);
    }
}

__global__ void scan_blocks_kernel() {
    __shared__ int sh[1024];
    int tid = threadIdx.x;
    int idx = blockIdx.x * 1024 + tid;
    int v = (idx < NN) ? g_cnt[idx] : 0;
    sh[tid] = v;
    __syncthreads();
    for (int off = 1; off < 1024; off <<= 1) {
        int t = 0;
        if (tid >= off) t = sh[tid - off];
        __syncthreads();
        sh[tid] += t;
        __syncthreads();
    }
    int incl = sh[tid];
    if (idx < NN) g_offs[idx] = incl - v;  // exclusive within block
    if (tid == 1023) g_bsum[blockIdx.x] = incl;
}

__global__ void scan_sums_kernel(int nblocks) {
    __shared__ int sh[128];
    int tid = threadIdx.x;
    int v = (tid < nblocks) ? g_bsum[tid] : 0;
    sh[tid] = v;
    __syncthreads();
    for (int off = 1; off < 128; off <<= 1) {
        int t = 0;
        if (tid >= off) t = sh[tid - off];
        __syncthreads();
        sh[tid] += t;
        __syncthreads();
    }
    if (tid < nblocks) g_bscan[tid] = sh[tid] - v;  // exclusive
}

__global__ void scan_add_kernel() {
    int i = blockIdx.x * blockDim.x + threadIdx.x;
    if (i < NN) {
        int off = g_offs[i] + g_bscan[i >> 10];
        g_offs[i] = off;
        g_cursor[i] = off;
        g_dinv[i] = rsqrtf((float)(g_cnt[i] + 1));  // +1 self-loop
        if (i == NN - 1) g_offs[NN] = off + g_cnt[i];
    }
}

__global__ void scatter_kernel(const void* __restrict__ ei) {
    int is64 = g_is64;
    for (int e = blockIdx.x * blockDim.x + threadIdx.x; e < EE; e += gridDim.x * blockDim.x) {
        int r = edge_row(ei, e, is64);
        int c = edge_col(ei, e, is64);
        int p = atomicAdd(&g_cursor[c], 1);
        g_adj[p] = r;
    }
}

// ---------------- GEMM1: g_xw[N,64] = x[N,128] @ W1[128,64] ----------------
// Block: 128 rows x 64 cols, 128 threads, each thread 8x8 register tile.
#define G1_SMEM ((128 * 64 + 128 * 132) * 4)

__global__ __launch_bounds__(128, 2) void gemm1_kernel(const float* __restrict__ A,
                                                       const float* __restrict__ W) {
    extern __shared__ float smem[];
    float* Ws = smem;               // [128][64]
    float* Xs = smem + 128 * 64;    // [128][132] padded
    int tid = threadIdx.x;
    int m0 = blockIdx.x * 128;
    int valid = NN - m0;

    // load W1 fully: 8192 floats = 2048 float4 / 128 threads = 16 each
    const float4* W4 = (const float4*)W;
    float4* Ws4 = (float4*)Ws;
#pragma unroll
    for (int i = 0; i < 16; i++) Ws4[tid + i * 128] = W4[tid + i * 128];

    // load X tile: 128 rows x 32 float4 = 4096 float4 / 128 = 32 each
#pragma unroll
    for (int j = 0; j < 32; j++) {
        int i = tid + j * 128;
        int row = i >> 5, k4 = i & 31;
        float4 v = make_float4(0.f, 0.f, 0.f, 0.f);
        if (row < valid) v = ((const float4*)A)[(size_t)(m0 + row) * 32 + k4];
        *(float4*)&Xs[row * 132 + k4 * 4] = v;
    }
    __syncthreads();

    int ty = tid >> 3, tx = tid & 7;
    int r0 = ty * 8, c0 = tx * 8;
    float acc[8][8];
#pragma unroll
    for (int i = 0; i < 8; i++)
#pragma unroll
        for (int j = 0; j < 8; j++) acc[i][j] = 0.f;

    for (int k = 0; k < 128; k += 4) {
        float4 a4[8];
#pragma unroll
        for (int i = 0; i < 8; i++) a4[i] = *(const float4*)&Xs[(r0 + i) * 132 + k];
#pragma unroll
        for (int kk = 0; kk < 4; kk++) {
            float4 b0 = *(const float4*)&Ws[(k + kk) * 64 + c0];
            float4 b1 = *(const float4*)&Ws[(k + kk) * 64 + c0 + 4];
            float bv[8] = {b0.x, b0.y, b0.z, b0.w, b1.x, b1.y, b1.z, b1.w};
#pragma unroll
            for (int i = 0; i < 8; i++) {
                float av = ((const float*)&a4[i])[kk];
#pragma unroll
                for (int j = 0; j < 8; j++) acc[i][j] = fmaf(av, bv[j], acc[i][j]);
            }
        }
    }

#pragma unroll
    for (int i = 0; i < 8; i++) {
        int row = m0 + r0 + i;
        if (row < NN) {
            float4 q0 = make_float4(acc[i][0], acc[i][1], acc[i][2], acc[i][3]);
            float4 q1 = make_float4(acc[i][4], acc[i][5], acc[i][6], acc[i][7]);
            *(float4*)&g_xw[(size_t)row * 64 + c0] = q0;
            *(float4*)&g_xw[(size_t)row * 64 + c0 + 4] = q1;
        }
    }
}

// ---------------- agg1: h1 = relu(dinv[c]*(sum dinv[r]*xw[r] + dinv[c]*xw[c]) + b1) ----------------
// 16 lanes per node, each lane one float4 (4 channels of 64).
__global__ void agg1_kernel(const float* __restrict__ b1) {
    int gid = blockIdx.x * blockDim.x + threadIdx.x;
    int node = gid >> 4;
    int lane = gid & 15;
    if (node >= NN) return;
    const float4* xw4 = (const float4*)g_xw;
    float di = g_dinv[node];
    float4 v = __ldg(&xw4[(size_t)node * 16 + lane]);
    float4 acc = make_float4(di * v.x, di * v.y, di * v.z, di * v.w);
    int s = g_offs[node], e = g_offs[node + 1];
    for (int k = s; k < e; k++) {
        int r = __ldg(&g_adj[k]);
        float w = __ldg(&g_dinv[r]);
        float4 u = __ldg(&xw4[(size_t)r * 16 + lane]);
        acc.x = fmaf(w, u.x, acc.x);
        acc.y = fmaf(w, u.y, acc.y);
        acc.z = fmaf(w, u.z, acc.z);
        acc.w = fmaf(w, u.w, acc.w);
    }
    float4 bb = __ldg(&((const float4*)b1)[lane]);
    float4 o;
    o.x = fmaxf(fmaf(di, acc.x, bb.x), 0.f);
    o.y = fmaxf(fmaf(di, acc.y, bb.y), 0.f);
    o.z = fmaxf(fmaf(di, acc.z, bb.z), 0.f);
    o.w = fmaxf(fmaf(di, acc.w, bb.w), 0.f);
    ((float4*)g_h1)[(size_t)node * 16 + lane] = o;
}

// ---------------- GEMM2: g_h2[N,40] = h1[N,64] @ W2[64,40] ----------------
__global__ __launch_bounds__(128, 2) void gemm2_kernel(const float* __restrict__ W) {
    __shared__ float Ws[64 * 40];     // 10240 B
    __shared__ float Xs[128 * 68];    // 34816 B
    int tid = threadIdx.x;
    int m0 = blockIdx.x * 128;
    int valid = NN - m0;

    // W2: 2560 floats = 640 float4 / 128 = 5 each
    const float4* W4 = (const float4*)W;
    float4* Ws4 = (float4*)Ws;
#pragma unroll
    for (int i = 0; i < 5; i++) Ws4[tid + i * 128] = W4[tid + i * 128];

    // X tile: 128 rows x 16 float4 = 2048 float4 / 128 = 16 each
#pragma unroll
    for (int j = 0; j < 16; j++) {
        int i = tid + j * 128;
        int row = i >> 4, k4 = i & 15;
        float4 v = make_float4(0.f, 0.f, 0.f, 0.f);
        if (row < valid) v = ((const float4*)g_h1)[(size_t)(m0 + row) * 16 + k4];
        *(float4*)&Xs[row * 68 + k4 * 4] = v;
    }
    __syncthreads();

    int ty = tid >> 3, tx = tid & 7;
    int r0 = ty * 8, c0 = tx * 5;
    float acc[8][5];
#pragma unroll
    for (int i = 0; i < 8; i++)
#pragma unroll
        for (int j = 0; j < 5; j++) acc[i][j] = 0.f;

    for (int k = 0; k < 64; k += 4) {
        float4 a4[8];
#pragma unroll
        for (int i = 0; i < 8; i++) a4[i] = *(const float4*)&Xs[(r0 + i) * 68 + k];
#pragma unroll
        for (int kk = 0; kk < 4; kk++) {
            float bv[5];
#pragma unroll
            for (int j = 0; j < 5; j++) bv[j] = Ws[(k + kk) * 40 + c0 + j];
#pragma unroll
            for (int i = 0; i < 8; i++) {
                float av = ((const float*)&a4[i])[kk];
#pragma unroll
                for (int j = 0; j < 5; j++) acc[i][j] = fmaf(av, bv[j], acc[i][j]);
            }
        }
    }

#pragma unroll
    for (int i = 0; i < 8; i++) {
        int row = m0 + r0 + i;
        if (row < NN) {
#pragma unroll
            for (int j = 0; j < 5; j++) g_h2[(size_t)row * 40 + c0 + j] = acc[i][j];
        }
    }
}

// ---------------- agg2: out = dinv[c]*(sum dinv[r]*h2[r] + dinv[c]*h2[c]) + b2 ----------------
// 10 lanes per node (3 nodes per warp, lanes 30,31 idle), each lane one float4 (4 of 40 ch).
__global__ void agg2_kernel(const float* __restrict__ b2, float* __restrict__ out) {
    int gtid = blockIdx.x * blockDim.x + threadIdx.x;
    int wid = gtid >> 5;
    int lane = gtid & 31;
    int g = lane / 10;
    int sub = lane % 10;
    if (g >= 3) return;
    int node = wid * 3 + g;
    if (node >= NN) return;
    const float4* h4 = (const float4*)g_h2;
    float di = g_dinv[node];
    float4 v = __ldg(&h4[(size_t)node * 10 + sub]);
    float4 acc = make_float4(di * v.x, di * v.y, di * v.z, di * v.w);
    int s = g_offs[node], e = g_offs[node + 1];
    for (int k = s; k < e; k++) {
        int r = __ldg(&g_adj[k]);
        float w = __ldg(&g_dinv[r]);
        float4 u = __ldg(&h4[(size_t)r * 10 + sub]);
        acc.x = fmaf(w, u.x, acc.x);
        acc.y = fmaf(w, u.y, acc.y);
        acc.z = fmaf(w, u.z, acc.z);
        acc.w = fmaf(w, u.w, acc.w);
    }
    float4 bb = __ldg(&((const float4*)b2)[sub]);
    float4 o;
    o.x = fmaf(di, acc.x, bb.x);
    o.y = fmaf(di, acc.y, bb.y);
    o.z = fmaf(di, acc.z, bb.z);
    o.w = fmaf(di, acc.w, bb.w);
    ((float4*)out)[(size_t)node * 10 + sub] = o;
}

// ---------------- launch ----------------
extern "C" void kernel_launch(void* const* d_in, const int* in_sizes, int n_in,
                              void* d_out, int out_size) {
    const float* x  = (const float*)d_in[0];
    const void*  ei = d_in[1];
    const float* W1 = (const float*)d_in[2];
    const float* b1 = (const float*)d_in[3];
    const float* W2 = (const float*)d_in[4];
    const float* b2 = (const float*)d_in[5];
    float* out = (float*)d_out;

    const int nscanblocks = (NN + 1023) / 1024;  // 98

    detect_kernel<<<1, 1>>>(ei);
    zero_cnt_kernel<<<(NN + 255) / 256, 256>>>();
    hist_kernel<<<2048, 256>>>(ei);
    scan_blocks_kernel<<<nscanblocks, 1024>>>();
    scan_sums_kernel<<<1, 128>>>(nscanblocks);
    scan_add_kernel<<<(NN + 255) / 256, 256>>>();
    scatter_kernel<<<2048, 256>>>(ei);

    cudaFuncSetAttribute(gemm1_kernel, cudaFuncAttributeMaxDynamicSharedMemorySize, G1_SMEM);
    gemm1_kernel<<<(NN + 127) / 128, 128, G1_SMEM>>>(x, W1);
    agg1_kernel<<<(NN * 16 + 255) / 256, 256>>>(b1);
    gemm2_kernel<<<(NN + 127) / 128, 128>>>(W2);
    agg2_kernel<<<(NN + 23) / 24 , 256>>>(b2, out);
}

// round 7
// speedup vs baseline: 1.1072x; 1.1072x over previous
#include <cuda_runtime.h>
#include <cuda_fp16.h>
#include <cstdint>

#define NN 100000
#define EE 1600000
#define INCH 128
#define HID 64
#define OUTC 40

// ---------------- scratch (device globals; no allocation allowed) ----------------
__device__ int     g_cnt[NN];
__device__ int     g_offs[NN + 1];
__device__ int     g_cursor[NN];
__device__ int     g_adj[EE];
__device__ float   g_dinv[NN];
__device__ __half  g_xw[(size_t)NN * HID];   // x @ W1   (fp16 for gather bandwidth)
__device__ float   g_h1[(size_t)NN * HID];   // relu(agg1) (fp32, dense reads only)
__device__ __half  g_h2[(size_t)NN * OUTC];  // h1 @ W2  (fp16 for gather bandwidth)
__device__ int     g_bsum[128];
__device__ int     g_bscan[128];
__device__ int     g_is64;

// ---------------- packed f32x2 helpers (FFMA2: 2x fp32 FMA rate on sm_103a) ----------------
__device__ __forceinline__ unsigned long long pk2(float lo, float hi) {
    unsigned long long r;
    asm("mov.b64 %0, {%1, %2};" : "=l"(r) : "f"(lo), "f"(hi));
    return r;
}
__device__ __forceinline__ void upk2(unsigned long long v, float& lo, float& hi) {
    asm("mov.b64 {%0, %1}, %2;" : "=f"(lo), "=f"(hi) : "l"(v));
}
__device__ __forceinline__ void fma2(unsigned long long& d, unsigned long long a,
                                     unsigned long long b) {
    asm("fma.rn.f32x2 %0, %1, %2, %0;" : "+l"(d) : "l"(a), "l"(b));
}

// ---------------- edge dtype sniffing (int64 vs int32) ----------------
__global__ void detect_kernel(const void* ei) {
    const unsigned int* w = (const unsigned int*)ei;
    int is64 = 1;
    for (int i = 0; i < 64; i++) {
        if (w[2 * i + 1] != 0u) { is64 = 0; break; }
    }
    g_is64 = is64;
}

__device__ __forceinline__ int edge_row(const void* ei, int e, int is64) {
    if (is64) return (int)((const long long*)ei)[e];
    return ((const int*)ei)[e];
}
__device__ __forceinline__ int edge_col(const void* ei, int e, int is64) {
    if (is64) return (int)((const long long*)ei)[EE + e];
    return ((const int*)ei)[EE + e];
}

// ---------------- CSR build ----------------
__global__ void zero_cnt_kernel() {
    int i = blockIdx.x * blockDim.x + threadIdx.x;
    if (i < NN) g_cnt[i] = 0;
}

__global__ void hist_kernel(const void* __restrict__ ei) {
    int is64 = g_is64;
    if (is64) {
        const longlong2* c2 = (const longlong2*)((const long long*)ei + EE);
        for (int e = blockIdx.x * blockDim.x + threadIdx.x; e < EE / 2;
             e += gridDim.x * blockDim.x) {
            longlong2 c = __ldg(&c2[e]);
            atomicAdd(&g_cnt[(int)c.x], 1);
            atomicAdd(&g_cnt[(int)c.y], 1);
        }
    } else {
        const int2* c2 = (const int2*)((const int*)ei + EE);
        for (int e = blockIdx.x * blockDim.x + threadIdx.x; e < EE / 2;
             e += gridDim.x * blockDim.x) {
            int2 c = __ldg(&c2[e]);
            atomicAdd(&g_cnt[c.x], 1);
            atomicAdd(&g_cnt[c.y], 1);
        }
    }
}

__global__ void scan_blocks_kernel() {
    __shared__ int ws[32];
    int tid = threadIdx.x;
    int idx = blockIdx.x * 1024 + tid;
    int v = (idx < NN) ? g_cnt[idx] : 0;
    int lane = tid & 31, wid = tid >> 5;
    int x = v;
#pragma unroll
    for (int o = 1; o < 32; o <<= 1) {
        int t = __shfl_up_sync(0xFFFFFFFFu, x, o);
        if (lane >= o) x += t;
    }
    if (lane == 31) ws[wid] = x;
    __syncthreads();
    if (wid == 0) {
        int s = ws[lane];
#pragma unroll
        for (int o = 1; o < 32; o <<= 1) {
            int t = __shfl_up_sync(0xFFFFFFFFu, s, o);
            if (lane >= o) s += t;
        }
        ws[lane] = s;
    }
    __syncthreads();
    int incl = x + (wid > 0 ? ws[wid - 1] : 0);
    if (idx < NN) g_offs[idx] = incl - v;  // exclusive within block
    if (tid == 1023) g_bsum[blockIdx.x] = incl;
}

__global__ void scan_sums_kernel(int nblocks) {
    __shared__ int sh[128];
    int tid = threadIdx.x;
    int v = (tid < nblocks) ? g_bsum[tid] : 0;
    sh[tid] = v;
    __syncthreads();
    for (int off = 1; off < 128; off <<= 1) {
        int t = 0;
        if (tid >= off) t = sh[tid - off];
        __syncthreads();
        sh[tid] += t;
        __syncthreads();
    }
    if (tid < nblocks) g_bscan[tid] = sh[tid] - v;  // exclusive
}

__global__ void scan_add_kernel() {
    int i = blockIdx.x * blockDim.x + threadIdx.x;
    if (i < NN) {
        int off = g_offs[i] + g_bscan[i >> 10];
        g_offs[i] = off;
        g_cursor[i] = off;
        g_dinv[i] = rsqrtf((float)(g_cnt[i] + 1));  // +1 self-loop
        if (i == NN - 1) g_offs[NN] = off + g_cnt[i];
    }
}

__global__ void scatter_kernel(const void* __restrict__ ei) {
    int is64 = g_is64;
    for (int e = blockIdx.x * blockDim.x + threadIdx.x; e < EE; e += gridDim.x * blockDim.x) {
        int r = edge_row(ei, e, is64);
        int c = edge_col(ei, e, is64);
        int p = atomicAdd(&g_cursor[c], 1);
        g_adj[p] = r;
    }
}

// ---------------- GEMM1: g_xw[N,64](fp16) = x[N,128] @ W1[128,64] ----------------
// Block: 128 rows x 64 cols, 128 threads, 8x8 register tile, packed f32x2 FMAs.
#define G1_SMEM ((128 * 64 + 128 * 132) * 4)

__global__ __launch_bounds__(128, 2) void gemm1_kernel(const float* __restrict__ A,
                                                       const float* __restrict__ W) {
    extern __shared__ float smem[];
    float* Ws = smem;               // [128][64]
    float* Xs = smem + 128 * 64;    // [128][132] padded
    int tid = threadIdx.x;
    int m0 = blockIdx.x * 128;
    int valid = NN - m0;

    const float4* W4 = (const float4*)W;
    float4* Ws4 = (float4*)Ws;
#pragma unroll
    for (int i = 0; i < 16; i++) Ws4[tid + i * 128] = W4[tid + i * 128];

#pragma unroll
    for (int j = 0; j < 32; j++) {
        int i = tid + j * 128;
        int row = i >> 5, k4 = i & 31;
        float4 v = make_float4(0.f, 0.f, 0.f, 0.f);
        if (row < valid) v = ((const float4*)A)[(size_t)(m0 + row) * 32 + k4];
        *(float4*)&Xs[row * 132 + k4 * 4] = v;
    }
    __syncthreads();

    int ty = tid >> 3, tx = tid & 7;
    int r0 = ty * 8, c0 = tx * 8;
    unsigned long long acc2[8][4];
#pragma unroll
    for (int i = 0; i < 8; i++)
#pragma unroll
        for (int j = 0; j < 4; j++) acc2[i][j] = pk2(0.f, 0.f);

    for (int k = 0; k < 128; k += 4) {
        float4 a4[8];
#pragma unroll
        for (int i = 0; i < 8; i++) a4[i] = *(const float4*)&Xs[(r0 + i) * 132 + k];
#pragma unroll
        for (int kk = 0; kk < 4; kk++) {
            float4 b0 = *(const float4*)&Ws[(k + kk) * 64 + c0];
            float4 b1 = *(const float4*)&Ws[(k + kk) * 64 + c0 + 4];
            unsigned long long bp[4];
            bp[0] = pk2(b0.x, b0.y);
            bp[1] = pk2(b0.z, b0.w);
            bp[2] = pk2(b1.x, b1.y);
            bp[3] = pk2(b1.z, b1.w);
#pragma unroll
            for (int i = 0; i < 8; i++) {
                float av = ((const float*)&a4[i])[kk];
                unsigned long long av2 = pk2(av, av);
#pragma unroll
                for (int j = 0; j < 4; j++) fma2(acc2[i][j], av2, bp[j]);
            }
        }
    }

#pragma unroll
    for (int i = 0; i < 8; i++) {
        int row = m0 + r0 + i;
        if (row < NN) {
            __half2 h[4];
#pragma unroll
            for (int j = 0; j < 4; j++) {
                float lo, hi;
                upk2(acc2[i][j], lo, hi);
                h[j] = __floats2half2_rn(lo, hi);
            }
            // 8 halves = 16B store; (row*64 + c0)*2 bytes with c0 % 8 == 0 -> 16B aligned
            *(uint4*)&g_xw[(size_t)row * 64 + c0] = *(const uint4*)h;
        }
    }
}

// ---------------- agg1: h1 = relu(dinv[c]*(sum dinv[r]*xw[r] + dinv[c]*xw[c]) + b1) ----------
// 16 lanes per node, each lane 4 fp16 channels (8B).
__global__ void agg1_kernel(const float* __restrict__ b1) {
    int gid = blockIdx.x * blockDim.x + threadIdx.x;
    int node = gid >> 4;
    int lane = gid & 15;
    if (node >= NN) return;
    const uint2* xw = (const uint2*)g_xw;  // 64 halves = 16 uint2 per row
    float di = g_dinv[node];

    uint2 sv = __ldg(&xw[(size_t)node * 16 + lane]);
    float2 s0 = __half22float2(*(const __half2*)&sv.x);
    float2 s1 = __half22float2(*(const __half2*)&sv.y);
    float4 acc = make_float4(di * s0.x, di * s0.y, di * s1.x, di * s1.y);

    int s = g_offs[node], e = g_offs[node + 1];
    int k = s;
    for (; k + 1 < e; k += 2) {
        int r0 = __ldg(&g_adj[k]);
        int r1 = __ldg(&g_adj[k + 1]);
        float w0 = __ldg(&g_dinv[r0]);
        float w1 = __ldg(&g_dinv[r1]);
        uint2 u0 = __ldg(&xw[(size_t)r0 * 16 + lane]);
        uint2 u1 = __ldg(&xw[(size_t)r1 * 16 + lane]);
        float2 a0 = __half22float2(*(const __half2*)&u0.x);
        float2 a1 = __half22float2(*(const __half2*)&u0.y);
        float2 c0 = __half22float2(*(const __half2*)&u1.x);
        float2 c1 = __half22float2(*(const __half2*)&u1.y);
        acc.x = fmaf(w0, a0.x, fmaf(w1, c0.x, acc.x));
        acc.y = fmaf(w0, a0.y, fmaf(w1, c0.y, acc.y));
        acc.z = fmaf(w0, a1.x, fmaf(w1, c1.x, acc.z));
        acc.w = fmaf(w0, a1.y, fmaf(w1, c1.y, acc.w));
    }
    if (k < e) {
        int r = __ldg(&g_adj[k]);
        float w = __ldg(&g_dinv[r]);
        uint2 u = __ldg(&xw[(size_t)r * 16 + lane]);
        float2 a0 = __half22float2(*(const __half2*)&u.x);
        float2 a1 = __half22float2(*(const __half2*)&u.y);
        acc.x = fmaf(w, a0.x, acc.x);
        acc.y = fmaf(w, a0.y, acc.y);
        acc.z = fmaf(w, a1.x, acc.z);
        acc.w = fmaf(w, a1.y, acc.w);
    }
    float4 bb = __ldg(&((const float4*)b1)[lane]);
    float4 o;
    o.x = fmaxf(fmaf(di, acc.x, bb.x), 0.f);
    o.y = fmaxf(fmaf(di, acc.y, bb.y), 0.f);
    o.z = fmaxf(fmaf(di, acc.z, bb.z), 0.f);
    o.w = fmaxf(fmaf(di, acc.w, bb.w), 0.f);
    ((float4*)g_h1)[(size_t)node * 16 + lane] = o;
}

// ---------------- GEMM2: g_h2[N,40](fp16) = h1[N,64] @ W2[64,40] ----------------
__global__ __launch_bounds__(128, 2) void gemm2_kernel(const float* __restrict__ W) {
    __shared__ float Ws[64 * 40];
    __shared__ float Xs[128 * 68];
    int tid = threadIdx.x;
    int m0 = blockIdx.x * 128;
    int valid = NN - m0;

    const float4* W4 = (const float4*)W;
    float4* Ws4 = (float4*)Ws;
#pragma unroll
    for (int i = 0; i < 5; i++) Ws4[tid + i * 128] = W4[tid + i * 128];

#pragma unroll
    for (int j = 0; j < 16; j++) {
        int i = tid + j * 128;
        int row = i >> 4, k4 = i & 15;
        float4 v = make_float4(0.f, 0.f, 0.f, 0.f);
        if (row < valid) v = ((const float4*)g_h1)[(size_t)(m0 + row) * 16 + k4];
        *(float4*)&Xs[row * 68 + k4 * 4] = v;
    }
    __syncthreads();

    int ty = tid >> 3, tx = tid & 7;
    int r0 = ty * 8, c0 = tx * 5;
    unsigned long long acc2[8][2];  // cols c0..c0+3 as 2 pairs
    float acc1[8];                  // col c0+4
#pragma unroll
    for (int i = 0; i < 8; i++) {
        acc2[i][0] = pk2(0.f, 0.f);
        acc2[i][1] = pk2(0.f, 0.f);
        acc1[i] = 0.f;
    }

    for (int k = 0; k < 64; k += 4) {
        float4 a4[8];
#pragma unroll
        for (int i = 0; i < 8; i++) a4[i] = *(const float4*)&Xs[(r0 + i) * 68 + k];
#pragma unroll
        for (int kk = 0; kk < 4; kk++) {
            const float* brow = &Ws[(k + kk) * 40 + c0];
            unsigned long long bp0 = pk2(brow[0], brow[1]);
            unsigned long long bp1 = pk2(brow[2], brow[3]);
            float b4 = brow[4];
#pragma unroll
            for (int i = 0; i < 8; i++) {
                float av = ((const float*)&a4[i])[kk];
                unsigned long long av2 = pk2(av, av);
                fma2(acc2[i][0], av2, bp0);
                fma2(acc2[i][1], av2, bp1);
                acc1[i] = fmaf(av, b4, acc1[i]);
            }
        }
    }

    // Epilogue: c0 = tx*5 is odd-aligned for odd tx -> scalar __half stores only
    // (ST.16 has no 4B alignment requirement; the half2 stores here crashed R5).
#pragma unroll
    for (int i = 0; i < 8; i++) {
        int row = m0 + r0 + i;
        if (row < NN) {
            float v0, v1, v2, v3;
            upk2(acc2[i][0], v0, v1);
            upk2(acc2[i][1], v2, v3);
            __half* dst = &g_h2[(size_t)row * 40 + c0];
            dst[0] = __float2half_rn(v0);
            dst[1] = __float2half_rn(v1);
            dst[2] = __float2half_rn(v2);
            dst[3] = __float2half_rn(v3);
            dst[4] = __float2half_rn(acc1[i]);
        }
    }
}

// ---------------- agg2: out = dinv[c]*(sum dinv[r]*h2[r] + dinv[c]*h2[c]) + b2 ----------------
// 10 lanes per node (3 nodes per warp), each lane 4 fp16 channels (8B).
__global__ void agg2_kernel(const float* __restrict__ b2, float* __restrict__ out) {
    int gtid = blockIdx.x * blockDim.x + threadIdx.x;
    int wid = gtid >> 5;
    int lane = gtid & 31;
    int g = lane / 10;
    int sub = lane % 10;
    if (g >= 3) return;
    int node = wid * 3 + g;
    if (node >= NN) return;
    const uint2* h4 = (const uint2*)g_h2;  // 40 halves = 10 uint2 per row
    float di = g_dinv[node];

    uint2 sv = __ldg(&h4[(size_t)node * 10 + sub]);
    float2 s0 = __half22float2(*(const __half2*)&sv.x);
    float2 s1 = __half22float2(*(const __half2*)&sv.y);
    float4 acc = make_float4(di * s0.x, di * s0.y, di * s1.x, di * s1.y);

    int s = g_offs[node], e = g_offs[node + 1];
    int k = s;
    for (; k + 1 < e; k += 2) {
        int r0 = __ldg(&g_adj[k]);
        int r1 = __ldg(&g_adj[k + 1]);
        float w0 = __ldg(&g_dinv[r0]);
        float w1 = __ldg(&g_dinv[r1]);
        uint2 u0 = __ldg(&h4[(size_t)r0 * 10 + sub]);
        uint2 u1 = __ldg(&h4[(size_t)r1 * 10 + sub]);
        float2 a0 = __half22float2(*(const __half2*)&u0.x);
        float2 a1 = __half22float2(*(const __half2*)&u0.y);
        float2 c0 = __half22float2(*(const __half2*)&u1.x);
        float2 c1 = __half22float2(*(const __half2*)&u1.y);
        acc.x = fmaf(w0, a0.x, fmaf(w1, c0.x, acc.x));
        acc.y = fmaf(w0, a0.y, fmaf(w1, c0.y, acc.y));
        acc.z = fmaf(w0, a1.x, fmaf(w1, c1.x, acc.z));
        acc.w = fmaf(w0, a1.y, fmaf(w1, c1.y, acc.w));
    }
    if (k < e) {
        int r = __ldg(&g_adj[k]);
        float w = __ldg(&g_dinv[r]);
        uint2 u = __ldg(&h4[(size_t)r * 10 + sub]);
        float2 a0 = __half22float2(*(const __half2*)&u.x);
        float2 a1 = __half22float2(*(const __half2*)&u.y);
        acc.x = fmaf(w, a0.x, acc.x);
        acc.y = fmaf(w, a0.y, acc.y);
        acc.z = fmaf(w, a1.x, acc.z);
        acc.w = fmaf(w, a1.y, acc.w);
    }
    float4 bb = __ldg(&((const float4*)b2)[sub]);
    float4 o;
    o.x = fmaf(di, acc.x, bb.x);
    o.y = fmaf(di, acc.y, bb.y);
    o.z = fmaf(di, acc.z, bb.z);
    o.w = fmaf(di, acc.w, bb.w);
    ((float4*)out)[(size_t)node * 10 + sub] = o;
}

// ---------------- launch ----------------
extern "C" void kernel_launch(void* const* d_in, const int* in_sizes, int n_in,
                              void* d_out, int out_size) {
    const float* x  = (const float*)d_in[0];
    const void*  ei = d_in[1];
    const float* W1 = (const float*)d_in[2];
    const float* b1 = (const float*)d_in[3];
    const float* W2 = (const float*)d_in[4];
    const float* b2 = (const float*)d_in[5];
    float* out = (float*)d_out;

    const int nscanblocks = (NN + 1023) / 1024;  // 98

    detect_kernel<<<1, 1>>>(ei);
    zero_cnt_kernel<<<(NN + 255) / 256, 256>>>();
    hist_kernel<<<1024, 256>>>(ei);
    scan_blocks_kernel<<<nscanblocks, 1024>>>();
    scan_sums_kernel<<<1, 128>>>(nscanblocks);
    scan_add_kernel<<<(NN + 255) / 256, 256>>>();
    scatter_kernel<<<2048, 256>>>(ei);

    cudaFuncSetAttribute(gemm1_kernel, cudaFuncAttributeMaxDynamicSharedMemorySize, G1_SMEM);
    gemm1_kernel<<<(NN + 127) / 128, 128, G1_SMEM>>>(x, W1);
    agg1_kernel<<<(NN * 16 + 255) / 256, 256>>>(b1);
    gemm2_kernel<<<(NN + 127) / 128, 128>>>(W2);
    agg2_kernel<<<(NN + 23) / 24, 256>>>(b2, out);
}

// round 8
// speedup vs baseline: 1.1632x; 1.0506x over previous
#include <cuda_runtime.h>
#include <cuda_fp16.h>
#include <cstdint>

#define NN 100000
#define EE 1600000
#define INCH 128
#define HID 64
#define OUTC 40

// ---------------- scratch (device globals; no allocation allowed) ----------------
__device__ int     g_cnt[NN];
__device__ int     g_offs[NN + 1];
__device__ int     g_cursor[NN];
__device__ int     g_adj[EE];
__device__ float   g_dinv[NN];
// fp16 feature arrays are gathered with LDG.128 -> force 16B alignment.
__device__ __align__(16) __half g_xw[(size_t)NN * HID];   // dinv[r] * (x @ W1)[r]  (premultiplied)
__device__ float   g_h1[(size_t)NN * HID];                // relu(agg1), fp32 dense
__device__ __align__(16) __half g_h2[(size_t)NN * OUTC];  // dinv[r] * (h1 @ W2)[r] (premultiplied)
__device__ int     g_bsum[128];
__device__ int     g_is64;

// ---------------- packed f32x2 helpers (FFMA2: 2x fp32 FMA rate on sm_103a) ----------------
__device__ __forceinline__ unsigned long long pk2(float lo, float hi) {
    unsigned long long r;
    asm("mov.b64 %0, {%1, %2};" : "=l"(r) : "f"(lo), "f"(hi));
    return r;
}
__device__ __forceinline__ void upk2(unsigned long long v, float& lo, float& hi) {
    asm("mov.b64 {%0, %1}, %2;" : "=f"(lo), "=f"(hi) : "l"(v));
}
__device__ __forceinline__ void fma2(unsigned long long& d, unsigned long long a,
                                     unsigned long long b) {
    asm("fma.rn.f32x2 %0, %1, %2, %0;" : "+l"(d) : "l"(a), "l"(b));
}

// ---------------- edge dtype helpers ----------------
__device__ __forceinline__ int edge_row(const void* ei, int e, int is64) {
    if (is64) return (int)((const long long*)ei)[e];
    return ((const int*)ei)[e];
}
__device__ __forceinline__ int edge_col(const void* ei, int e, int is64) {
    if (is64) return (int)((const long long*)ei)[EE + e];
    return ((const int*)ei)[EE + e];
}

// ---------------- init: zero counters + dtype sniff (fused) ----------------
__global__ void init_kernel(const void* ei) {
    int i = blockIdx.x * blockDim.x + threadIdx.x;
    if (i < NN) g_cnt[i] = 0;
    if (i == 0) {
        const unsigned int* w = (const unsigned int*)ei;
        int is64 = 1;
        for (int j = 0; j < 64; j++) {
            if (w[2 * j + 1] != 0u) { is64 = 0; break; }
        }
        g_is64 = is64;
    }
}

__global__ void hist_kernel(const void* __restrict__ ei) {
    int is64 = g_is64;
    if (is64) {
        const longlong2* c2 = (const longlong2*)((const long long*)ei + EE);
        for (int e = blockIdx.x * blockDim.x + threadIdx.x; e < EE / 2;
             e += gridDim.x * blockDim.x) {
            longlong2 c = __ldg(&c2[e]);
            atomicAdd(&g_cnt[(int)c.x], 1);
            atomicAdd(&g_cnt[(int)c.y], 1);
        }
    } else {
        const int2* c2 = (const int2*)((const int*)ei + EE);
        for (int e = blockIdx.x * blockDim.x + threadIdx.x; e < EE / 2;
             e += gridDim.x * blockDim.x) {
            int2 c = __ldg(&c2[e]);
            atomicAdd(&g_cnt[c.x], 1);
            atomicAdd(&g_cnt[c.y], 1);
        }
    }
}

__global__ void scan_blocks_kernel() {
    __shared__ int ws[32];
    int tid = threadIdx.x;
    int idx = blockIdx.x * 1024 + tid;
    int v = (idx < NN) ? g_cnt[idx] : 0;
    int lane = tid & 31, wid = tid >> 5;
    int x = v;
#pragma unroll
    for (int o = 1; o < 32; o <<= 1) {
        int t = __shfl_up_sync(0xFFFFFFFFu, x, o);
        if (lane >= o) x += t;
    }
    if (lane == 31) ws[wid] = x;
    __syncthreads();
    if (wid == 0) {
        int s = ws[lane];
#pragma unroll
        for (int o = 1; o < 32; o <<= 1) {
            int t = __shfl_up_sync(0xFFFFFFFFu, s, o);
            if (lane >= o) s += t;
        }
        ws[lane] = s;
    }
    __syncthreads();
    int incl = x + (wid > 0 ? ws[wid - 1] : 0);
    if (idx < NN) g_offs[idx] = incl - v;  // exclusive within block
    if (tid == 1023) g_bsum[blockIdx.x] = incl;
}

// Fused: every block redundantly scans the 98 block sums (cheap), then applies
// its carry, writes offsets/cursors/dinv. Replaces scan_sums + scan_add.
__global__ void scan_finish_kernel() {
    __shared__ int sh[128];
    int tid = threadIdx.x;
    if (tid < 128) sh[tid] = (tid < 98) ? g_bsum[tid] : 0;
    __syncthreads();
    for (int off = 1; off < 128; off <<= 1) {
        int t = 0;
        if (tid < 128 && tid >= off) t = sh[tid - off];
        __syncthreads();
        if (tid < 128) sh[tid] += t;
        __syncthreads();
    }
    int carry = (blockIdx.x > 0) ? sh[blockIdx.x - 1] : 0;
    int i = blockIdx.x * 1024 + tid;
    if (i < NN) {
        int off = g_offs[i] + carry;
        g_offs[i] = off;
        g_cursor[i] = off;
        g_dinv[i] = rsqrtf((float)(g_cnt[i] + 1));  // +1 self-loop
    }
    if (blockIdx.x == 0 && tid == 0) g_offs[NN] = sh[127];
}

__global__ void scatter_kernel(const void* __restrict__ ei) {
    int is64 = g_is64;
    for (int e = blockIdx.x * blockDim.x + threadIdx.x; e < EE; e += gridDim.x * blockDim.x) {
        int r = edge_row(ei, e, is64);
        int c = edge_col(ei, e, is64);
        int p = atomicAdd(&g_cursor[c], 1);
        g_adj[p] = r;
    }
}

// ---------------- GEMM1: g_xw[N,64](fp16) = dinv[row] * (x[N,128] @ W1[128,64]) -------------
#define G1_SMEM ((128 * 64 + 128 * 132) * 4)

__global__ __launch_bounds__(128, 2) void gemm1_kernel(const float* __restrict__ A,
                                                       const float* __restrict__ W) {
    extern __shared__ float smem[];
    float* Ws = smem;               // [128][64]
    float* Xs = smem + 128 * 64;    // [128][132] padded
    int tid = threadIdx.x;
    int m0 = blockIdx.x * 128;
    int valid = NN - m0;

    const float4* W4 = (const float4*)W;
    float4* Ws4 = (float4*)Ws;
#pragma unroll
    for (int i = 0; i < 16; i++) Ws4[tid + i * 128] = W4[tid + i * 128];

#pragma unroll
    for (int j = 0; j < 32; j++) {
        int i = tid + j * 128;
        int row = i >> 5, k4 = i & 31;
        float4 v = make_float4(0.f, 0.f, 0.f, 0.f);
        if (row < valid) v = ((const float4*)A)[(size_t)(m0 + row) * 32 + k4];
        *(float4*)&Xs[row * 132 + k4 * 4] = v;
    }
    __syncthreads();

    int ty = tid >> 3, tx = tid & 7;
    int r0 = ty * 8, c0 = tx * 8;
    unsigned long long acc2[8][4];
#pragma unroll
    for (int i = 0; i < 8; i++)
#pragma unroll
        for (int j = 0; j < 4; j++) acc2[i][j] = pk2(0.f, 0.f);

    for (int k = 0; k < 128; k += 4) {
        float4 a4[8];
#pragma unroll
        for (int i = 0; i < 8; i++) a4[i] = *(const float4*)&Xs[(r0 + i) * 132 + k];
#pragma unroll
        for (int kk = 0; kk < 4; kk++) {
            float4 b0 = *(const float4*)&Ws[(k + kk) * 64 + c0];
            float4 b1 = *(const float4*)&Ws[(k + kk) * 64 + c0 + 4];
            unsigned long long bp[4];
            bp[0] = pk2(b0.x, b0.y);
            bp[1] = pk2(b0.z, b0.w);
            bp[2] = pk2(b1.x, b1.y);
            bp[3] = pk2(b1.z, b1.w);
#pragma unroll
            for (int i = 0; i < 8; i++) {
                float av = ((const float*)&a4[i])[kk];
                unsigned long long av2 = pk2(av, av);
#pragma unroll
                for (int j = 0; j < 4; j++) fma2(acc2[i][j], av2, bp[j]);
            }
        }
    }

#pragma unroll
    for (int i = 0; i < 8; i++) {
        int row = m0 + r0 + i;
        if (row < NN) {
            float di = __ldg(&g_dinv[row]);  // premultiply dinv into stored features
            __half2 h[4];
#pragma unroll
            for (int j = 0; j < 4; j++) {
                float lo, hi;
                upk2(acc2[i][j], lo, hi);
                h[j] = __floats2half2_rn(di * lo, di * hi);
            }
            *(uint4*)&g_xw[(size_t)row * 64 + c0] = *(const uint4*)h;  // 16B aligned (c0%8==0)
        }
    }
}

// ---------------- agg1: h1 = relu(dinv[c]*(sum_r scaled[r] + scaled[c]) + b1) ----------------
// 8 lanes per node; each lane handles 8 fp16 channels (16B LDG.128). 4-deep unrolled gathers.
__global__ void agg1_kernel(const float* __restrict__ b1) {
    int gid = blockIdx.x * blockDim.x + threadIdx.x;
    int node = gid >> 3;
    int lane = gid & 7;
    if (node >= NN) return;
    const uint4* xw = (const uint4*)g_xw;  // 64 halves = 8 uint4 per row

    float acc[8];
    {
        uint4 sv = __ldg(&xw[(size_t)node * 8 + lane]);  // = dinv[c]*h[c]  (self term)
        const __half2* hp = (const __half2*)&sv;
#pragma unroll
        for (int j = 0; j < 4; j++) {
            float2 f = __half22float2(hp[j]);
            acc[2 * j] = f.x;
            acc[2 * j + 1] = f.y;
        }
    }

    int s = g_offs[node], e = g_offs[node + 1];
    int k = s;
    for (; k + 4 <= e; k += 4) {
        int r0 = __ldg(&g_adj[k]);
        int r1 = __ldg(&g_adj[k + 1]);
        int r2 = __ldg(&g_adj[k + 2]);
        int r3 = __ldg(&g_adj[k + 3]);
        uint4 u0 = __ldg(&xw[(size_t)r0 * 8 + lane]);
        uint4 u1 = __ldg(&xw[(size_t)r1 * 8 + lane]);
        uint4 u2 = __ldg(&xw[(size_t)r2 * 8 + lane]);
        uint4 u3 = __ldg(&xw[(size_t)r3 * 8 + lane]);
        const __half2* p0 = (const __half2*)&u0;
        const __half2* p1 = (const __half2*)&u1;
        const __half2* p2 = (const __half2*)&u2;
        const __half2* p3 = (const __half2*)&u3;
#pragma unroll
        for (int j = 0; j < 4; j++) {
            float2 f0 = __half22float2(p0[j]);
            float2 f1 = __half22float2(p1[j]);
            float2 f2 = __half22float2(p2[j]);
            float2 f3 = __half22float2(p3[j]);
            acc[2 * j]     += (f0.x + f1.x) + (f2.x + f3.x);
            acc[2 * j + 1] += (f0.y + f1.y) + (f2.y + f3.y);
        }
    }
    for (; k < e; k++) {
        int r = __ldg(&g_adj[k]);
        uint4 u = __ldg(&xw[(size_t)r * 8 + lane]);
        const __half2* p = (const __half2*)&u;
#pragma unroll
        for (int j = 0; j < 4; j++) {
            float2 f = __half22float2(p[j]);
            acc[2 * j] += f.x;
            acc[2 * j + 1] += f.y;
        }
    }

    float di = __ldg(&g_dinv[node]);
    const float4* b14 = (const float4*)b1;
    float4 bb0 = __ldg(&b14[lane * 2]);
    float4 bb1 = __ldg(&b14[lane * 2 + 1]);
    float4 o0, o1;
    o0.x = fmaxf(fmaf(di, acc[0], bb0.x), 0.f);
    o0.y = fmaxf(fmaf(di, acc[1], bb0.y), 0.f);
    o0.z = fmaxf(fmaf(di, acc[2], bb0.z), 0.f);
    o0.w = fmaxf(fmaf(di, acc[3], bb0.w), 0.f);
    o1.x = fmaxf(fmaf(di, acc[4], bb1.x), 0.f);
    o1.y = fmaxf(fmaf(di, acc[5], bb1.y), 0.f);
    o1.z = fmaxf(fmaf(di, acc[6], bb1.z), 0.f);
    o1.w = fmaxf(fmaf(di, acc[7], bb1.w), 0.f);
    float4* dst = (float4*)&g_h1[(size_t)node * 64 + lane * 8];
    dst[0] = o0;
    dst[1] = o1;
}

// ---------------- GEMM2: g_h2[N,40](fp16) = dinv[row] * (h1[N,64] @ W2[64,40]) --------------
__global__ __launch_bounds__(128, 2) void gemm2_kernel(const float* __restrict__ W) {
    __shared__ float Ws[64 * 40];
    __shared__ float Xs[128 * 68];
    int tid = threadIdx.x;
    int m0 = blockIdx.x * 128;
    int valid = NN - m0;

    const float4* W4 = (const float4*)W;
    float4* Ws4 = (float4*)Ws;
#pragma unroll
    for (int i = 0; i < 5; i++) Ws4[tid + i * 128] = W4[tid + i * 128];

#pragma unroll
    for (int j = 0; j < 16; j++) {
        int i = tid + j * 128;
        int row = i >> 4, k4 = i & 15;
        float4 v = make_float4(0.f, 0.f, 0.f, 0.f);
        if (row < valid) v = ((const float4*)g_h1)[(size_t)(m0 + row) * 16 + k4];
        *(float4*)&Xs[row * 68 + k4 * 4] = v;
    }
    __syncthreads();

    int ty = tid >> 3, tx = tid & 7;
    int r0 = ty * 8, c0 = tx * 5;
    unsigned long long acc2[8][2];
    float acc1[8];
#pragma unroll
    for (int i = 0; i < 8; i++) {
        acc2[i][0] = pk2(0.f, 0.f);
        acc2[i][1] = pk2(0.f, 0.f);
        acc1[i] = 0.f;
    }

    for (int k = 0; k < 64; k += 4) {
        float4 a4[8];
#pragma unroll
        for (int i = 0; i < 8; i++) a4[i] = *(const float4*)&Xs[(r0 + i) * 68 + k];
#pragma unroll
        for (int kk = 0; kk < 4; kk++) {
            const float* brow = &Ws[(k + kk) * 40 + c0];
            unsigned long long bp0 = pk2(brow[0], brow[1]);
            unsigned long long bp1 = pk2(brow[2], brow[3]);
            float b4 = brow[4];
#pragma unroll
            for (int i = 0; i < 8; i++) {
                float av = ((const float*)&a4[i])[kk];
                unsigned long long av2 = pk2(av, av);
                fma2(acc2[i][0], av2, bp0);
                fma2(acc2[i][1], av2, bp1);
                acc1[i] = fmaf(av, b4, acc1[i]);
            }
        }
    }

    // Scalar __half stores only: c0 = tx*5 is odd for odd tx (no half2 alignment).
#pragma unroll
    for (int i = 0; i < 8; i++) {
        int row = m0 + r0 + i;
        if (row < NN) {
            float di = __ldg(&g_dinv[row]);
            float v0, v1, v2, v3;
            upk2(acc2[i][0], v0, v1);
            upk2(acc2[i][1], v2, v3);
            __half* dst = &g_h2[(size_t)row * 40 + c0];
            dst[0] = __float2half_rn(di * v0);
            dst[1] = __float2half_rn(di * v1);
            dst[2] = __float2half_rn(di * v2);
            dst[3] = __float2half_rn(di * v3);
            dst[4] = __float2half_rn(di * acc1[i]);
        }
    }
}

// ---------------- agg2: out = dinv[c]*(sum_r scaled[r] + scaled[c]) + b2 ----------------
// 5 lanes per node (6 nodes per warp, lanes 30,31 idle); each lane 8 fp16 ch (16B LDG.128).
__global__ void agg2_kernel(const float* __restrict__ b2, float* __restrict__ out) {
    int gtid = blockIdx.x * blockDim.x + threadIdx.x;
    int wid = gtid >> 5;
    int lane = gtid & 31;
    int g = lane / 5;
    int sub = lane - g * 5;
    if (g >= 6) return;
    int node = wid * 6 + g;
    if (node >= NN) return;
    const uint4* hh = (const uint4*)g_h2;  // 40 halves = 5 uint4 per row

    float acc[8];
    {
        uint4 sv = __ldg(&hh[(size_t)node * 5 + sub]);
        const __half2* hp = (const __half2*)&sv;
#pragma unroll
        for (int j = 0; j < 4; j++) {
            float2 f = __half22float2(hp[j]);
            acc[2 * j] = f.x;
            acc[2 * j + 1] = f.y;
        }
    }

    int s = g_offs[node], e = g_offs[node + 1];
    int k = s;
    for (; k + 4 <= e; k += 4) {
        int r0 = __ldg(&g_adj[k]);
        int r1 = __ldg(&g_adj[k + 1]);
        int r2 = __ldg(&g_adj[k + 2]);
        int r3 = __ldg(&g_adj[k + 3]);
        uint4 u0 = __ldg(&hh[(size_t)r0 * 5 + sub]);
        uint4 u1 = __ldg(&hh[(size_t)r1 * 5 + sub]);
        uint4 u2 = __ldg(&hh[(size_t)r2 * 5 + sub]);
        uint4 u3 = __ldg(&hh[(size_t)r3 * 5 + sub]);
        const __half2* p0 = (const __half2*)&u0;
        const __half2* p1 = (const __half2*)&u1;
        const __half2* p2 = (const __half2*)&u2;
        const __half2* p3 = (const __half2*)&u3;
#pragma unroll
        for (int j = 0; j < 4; j++) {
            float2 f0 = __half22float2(p0[j]);
            float2 f1 = __half22float2(p1[j]);
            float2 f2 = __half22float2(p2[j]);
            float2 f3 = __half22float2(p3[j]);
            acc[2 * j]     += (f0.x + f1.x) + (f2.x + f3.x);
            acc[2 * j + 1] += (f0.y + f1.y) + (f2.y + f3.y);
        }
    }
    for (; k < e; k++) {
        int r = __ldg(&g_adj[k]);
        uint4 u = __ldg(&hh[(size_t)r * 5 + sub]);
        const __half2* p = (const __half2*)&u;
#pragma unroll
        for (int j = 0; j < 4; j++) {
            float2 f = __half22float2(p[j]);
            acc[2 * j] += f.x;
            acc[2 * j + 1] += f.y;
        }
    }

    float di = __ldg(&g_dinv[node]);
    const float4* b24 = (const float4*)b2;
    float4 bb0 = __ldg(&b24[sub * 2]);
    float4 bb1 = __ldg(&b24[sub * 2 + 1]);
    float4 o0, o1;
    o0.x = fmaf(di, acc[0], bb0.x);
    o0.y = fmaf(di, acc[1], bb0.y);
    o0.z = fmaf(di, acc[2], bb0.z);
    o0.w = fmaf(di, acc[3], bb0.w);
    o1.x = fmaf(di, acc[4], bb1.x);
    o1.y = fmaf(di, acc[5], bb1.y);
    o1.z = fmaf(di, acc[6], bb1.z);
    o1.w = fmaf(di, acc[7], bb1.w);
    float4* dst = (float4*)&out[(size_t)node * 40 + sub * 8];
    dst[0] = o0;
    dst[1] = o1;
}

// ---------------- launch ----------------
extern "C" void kernel_launch(void* const* d_in, const int* in_sizes, int n_in,
                              void* d_out, int out_size) {
    const float* x  = (const float*)d_in[0];
    const void*  ei = d_in[1];
    const float* W1 = (const float*)d_in[2];
    const float* b1 = (const float*)d_in[3];
    const float* W2 = (const float*)d_in[4];
    const float* b2 = (const float*)d_in[5];
    float* out = (float*)d_out;

    const int nscanblocks = (NN + 1023) / 1024;  // 98

    init_kernel<<<(NN + 255) / 256, 256>>>(ei);
    hist_kernel<<<1024, 256>>>(ei);
    scan_blocks_kernel<<<nscanblocks, 1024>>>();
    scan_finish_kernel<<<nscanblocks, 1024>>>();
    scatter_kernel<<<2048, 256>>>(ei);

    cudaFuncSetAttribute(gemm1_kernel, cudaFuncAttributeMaxDynamicSharedMemorySize, G1_SMEM);
    gemm1_kernel<<<(NN + 127) / 128, 128, G1_SMEM>>>(x, W1);
    agg1_kernel<<<(NN * 8 + 255) / 256, 256>>>(b1);
    gemm2_kernel<<<(NN + 127) / 128, 128>>>(W2);
    // 256 threads = 8 warps = 48 nodes per block
    agg2_kernel<<<(NN + 47) / 48, 256>>>(b2, out);
}

// round 9
// speedup vs baseline: 1.2346x; 1.0613x over previous
#include <cuda_runtime.h>
#include <cuda_fp16.h>
#include <cstdint>

#define NN 100000
#define EE 1600000
#define INCH 128
#define HID 64
#define OUTC 40
#define ELLW 64   // max degree capacity; Poisson(16) -> P(deg>=64) ~ e^-40, safe

// ---------------- scratch (device globals; no allocation allowed) ----------------
__device__ int     g_cnt[NN];
__device__ int     g_adj[(size_t)NN * ELLW];   // ELL adjacency: sources of edges into node
__device__ float   g_dinv[NN];
// fp16 feature arrays are gathered with LDG.128 -> force 16B alignment.
__device__ __align__(16) __half g_xw[(size_t)NN * HID];   // dinv[r] * (x @ W1)[r]  (premultiplied)
__device__ float   g_h1[(size_t)NN * HID];                // relu(agg1), fp32 dense
__device__ __align__(16) __half g_h2[(size_t)NN * OUTC];  // dinv[r] * (h1 @ W2)[r] (premultiplied)
__device__ int     g_is64;

// ---------------- packed f32x2 helpers (FFMA2: 2x fp32 FMA rate on sm_103a) ----------------
__device__ __forceinline__ unsigned long long pk2(float lo, float hi) {
    unsigned long long r;
    asm("mov.b64 %0, {%1, %2};" : "=l"(r) : "f"(lo), "f"(hi));
    return r;
}
__device__ __forceinline__ void upk2(unsigned long long v, float& lo, float& hi) {
    asm("mov.b64 {%0, %1}, %2;" : "=f"(lo), "=f"(hi) : "l"(v));
}
__device__ __forceinline__ void fma2(unsigned long long& d, unsigned long long a,
                                     unsigned long long b) {
    asm("fma.rn.f32x2 %0, %1, %2, %0;" : "+l"(d) : "l"(a), "l"(b));
}

// ---------------- init: zero counters + dtype sniff (fused) ----------------
__global__ void init_kernel(const void* ei) {
    int i = blockIdx.x * blockDim.x + threadIdx.x;
    if (i < NN) g_cnt[i] = 0;
    if (i == 0) {
        const unsigned int* w = (const unsigned int*)ei;
        int is64 = 1;
        for (int j = 0; j < 64; j++) {
            if (w[2 * j + 1] != 0u) { is64 = 0; break; }
        }
        g_is64 = is64;
    }
}

// ---------------- single-pass ELL build: count + place in one sweep ----------------
__global__ void scatter_ell_kernel(const void* __restrict__ ei) {
    int is64 = g_is64;
    int tid = blockIdx.x * blockDim.x + threadIdx.x;
    int stride = gridDim.x * blockDim.x;
    if (is64) {
        const longlong2* r2 = (const longlong2*)ei;
        const longlong2* c2 = (const longlong2*)((const long long*)ei + EE);
        for (int e = tid; e < EE / 2; e += stride) {
            longlong2 rr = __ldg(&r2[e]);
            longlong2 cc = __ldg(&c2[e]);
            int c0 = (int)cc.x, c1 = (int)cc.y;
            int p0 = atomicAdd(&g_cnt[c0], 1);
            int p1 = atomicAdd(&g_cnt[c1], 1);
            g_adj[(size_t)c0 * ELLW + p0] = (int)rr.x;
            g_adj[(size_t)c1 * ELLW + p1] = (int)rr.y;
        }
    } else {
        const int2* r2 = (const int2*)ei;
        const int2* c2 = (const int2*)((const int*)ei + EE);
        for (int e = tid; e < EE / 2; e += stride) {
            int2 rr = __ldg(&r2[e]);
            int2 cc = __ldg(&c2[e]);
            int p0 = atomicAdd(&g_cnt[cc.x], 1);
            int p1 = atomicAdd(&g_cnt[cc.y], 1);
            g_adj[(size_t)cc.x * ELLW + p0] = rr.x;
            g_adj[(size_t)cc.y * ELLW + p1] = rr.y;
        }
    }
}

__global__ void dinv_kernel() {
    int i = blockIdx.x * blockDim.x + threadIdx.x;
    if (i < NN) g_dinv[i] = rsqrtf((float)(g_cnt[i] + 1));  // +1 self-loop
}

// ---------------- GEMM1: g_xw[N,64](fp16) = dinv[row] * (x[N,128] @ W1[128,64]) -------------
#define G1_SMEM ((128 * 64 + 128 * 132) * 4)

__global__ __launch_bounds__(128, 2) void gemm1_kernel(const float* __restrict__ A,
                                                       const float* __restrict__ W) {
    extern __shared__ float smem[];
    float* Ws = smem;               // [128][64]
    float* Xs = smem + 128 * 64;    // [128][132] padded
    int tid = threadIdx.x;
    int m0 = blockIdx.x * 128;
    int valid = NN - m0;

    const float4* W4 = (const float4*)W;
    float4* Ws4 = (float4*)Ws;
#pragma unroll
    for (int i = 0; i < 16; i++) Ws4[tid + i * 128] = W4[tid + i * 128];

#pragma unroll
    for (int j = 0; j < 32; j++) {
        int i = tid + j * 128;
        int row = i >> 5, k4 = i & 31;
        float4 v = make_float4(0.f, 0.f, 0.f, 0.f);
        if (row < valid) v = ((const float4*)A)[(size_t)(m0 + row) * 32 + k4];
        *(float4*)&Xs[row * 132 + k4 * 4] = v;
    }
    __syncthreads();

    int ty = tid >> 3, tx = tid & 7;
    int r0 = ty * 8, c0 = tx * 8;
    unsigned long long acc2[8][4];
#pragma unroll
    for (int i = 0; i < 8; i++)
#pragma unroll
        for (int j = 0; j < 4; j++) acc2[i][j] = pk2(0.f, 0.f);

    for (int k = 0; k < 128; k += 4) {
        float4 a4[8];
#pragma unroll
        for (int i = 0; i < 8; i++) a4[i] = *(const float4*)&Xs[(r0 + i) * 132 + k];
#pragma unroll
        for (int kk = 0; kk < 4; kk++) {
            float4 b0 = *(const float4*)&Ws[(k + kk) * 64 + c0];
            float4 b1 = *(const float4*)&Ws[(k + kk) * 64 + c0 + 4];
            unsigned long long bp[4];
            bp[0] = pk2(b0.x, b0.y);
            bp[1] = pk2(b0.z, b0.w);
            bp[2] = pk2(b1.x, b1.y);
            bp[3] = pk2(b1.z, b1.w);
#pragma unroll
            for (int i = 0; i < 8; i++) {
                float av = ((const float*)&a4[i])[kk];
                unsigned long long av2 = pk2(av, av);
#pragma unroll
                for (int j = 0; j < 4; j++) fma2(acc2[i][j], av2, bp[j]);
            }
        }
    }

#pragma unroll
    for (int i = 0; i < 8; i++) {
        int row = m0 + r0 + i;
        if (row < NN) {
            float di = __ldg(&g_dinv[row]);  // premultiply dinv into stored features
            __half2 h[4];
#pragma unroll
            for (int j = 0; j < 4; j++) {
                float lo, hi;
                upk2(acc2[i][j], lo, hi);
                h[j] = __floats2half2_rn(di * lo, di * hi);
            }
            *(uint4*)&g_xw[(size_t)row * 64 + c0] = *(const uint4*)h;  // 16B aligned (c0%8==0)
        }
    }
}

// ---------------- agg1: h1 = relu(dinv[c]*(sum_r scaled[r] + scaled[c]) + b1) ----------------
// 8 lanes per node; each lane handles 8 fp16 channels (16B LDG.128). 4-deep unrolled gathers.
__global__ void agg1_kernel(const float* __restrict__ b1) {
    int gid = blockIdx.x * blockDim.x + threadIdx.x;
    int node = gid >> 3;
    int lane = gid & 7;
    if (node >= NN) return;
    const uint4* xw = (const uint4*)g_xw;  // 64 halves = 8 uint4 per row

    float acc[8];
    {
        uint4 sv = __ldg(&xw[(size_t)node * 8 + lane]);  // = dinv[c]*h[c]  (self term)
        const __half2* hp = (const __half2*)&sv;
#pragma unroll
        for (int j = 0; j < 4; j++) {
            float2 f = __half22float2(hp[j]);
            acc[2 * j] = f.x;
            acc[2 * j + 1] = f.y;
        }
    }

    int s = node * ELLW;
    int e = s + __ldg(&g_cnt[node]);
    int k = s;
    for (; k + 4 <= e; k += 4) {
        int r0 = __ldg(&g_adj[k]);
        int r1 = __ldg(&g_adj[k + 1]);
        int r2 = __ldg(&g_adj[k + 2]);
        int r3 = __ldg(&g_adj[k + 3]);
        uint4 u0 = __ldg(&xw[(size_t)r0 * 8 + lane]);
        uint4 u1 = __ldg(&xw[(size_t)r1 * 8 + lane]);
        uint4 u2 = __ldg(&xw[(size_t)r2 * 8 + lane]);
        uint4 u3 = __ldg(&xw[(size_t)r3 * 8 + lane]);
        const __half2* p0 = (const __half2*)&u0;
        const __half2* p1 = (const __half2*)&u1;
        const __half2* p2 = (const __half2*)&u2;
        const __half2* p3 = (const __half2*)&u3;
#pragma unroll
        for (int j = 0; j < 4; j++) {
            float2 f0 = __half22float2(p0[j]);
            float2 f1 = __half22float2(p1[j]);
            float2 f2 = __half22float2(p2[j]);
            float2 f3 = __half22float2(p3[j]);
            acc[2 * j]     += (f0.x + f1.x) + (f2.x + f3.x);
            acc[2 * j + 1] += (f0.y + f1.y) + (f2.y + f3.y);
        }
    }
    for (; k < e; k++) {
        int r = __ldg(&g_adj[k]);
        uint4 u = __ldg(&xw[(size_t)r * 8 + lane]);
        const __half2* p = (const __half2*)&u;
#pragma unroll
        for (int j = 0; j < 4; j++) {
            float2 f = __half22float2(p[j]);
            acc[2 * j] += f.x;
            acc[2 * j + 1] += f.y;
        }
    }

    float di = __ldg(&g_dinv[node]);
    const float4* b14 = (const float4*)b1;
    float4 bb0 = __ldg(&b14[lane * 2]);
    float4 bb1 = __ldg(&b14[lane * 2 + 1]);
    float4 o0, o1;
    o0.x = fmaxf(fmaf(di, acc[0], bb0.x), 0.f);
    o0.y = fmaxf(fmaf(di, acc[1], bb0.y), 0.f);
    o0.z = fmaxf(fmaf(di, acc[2], bb0.z), 0.f);
    o0.w = fmaxf(fmaf(di, acc[3], bb0.w), 0.f);
    o1.x = fmaxf(fmaf(di, acc[4], bb1.x), 0.f);
    o1.y = fmaxf(fmaf(di, acc[5], bb1.y), 0.f);
    o1.z = fmaxf(fmaf(di, acc[6], bb1.z), 0.f);
    o1.w = fmaxf(fmaf(di, acc[7], bb1.w), 0.f);
    float4* dst = (float4*)&g_h1[(size_t)node * 64 + lane * 8];
    dst[0] = o0;
    dst[1] = o1;
}

// ---------------- GEMM2: g_h2[N,40](fp16) = dinv[row] * (h1[N,64] @ W2[64,40]) --------------
__global__ __launch_bounds__(128, 2) void gemm2_kernel(const float* __restrict__ W) {
    __shared__ float Ws[64 * 40];
    __shared__ float Xs[128 * 68];
    int tid = threadIdx.x;
    int m0 = blockIdx.x * 128;
    int valid = NN - m0;

    const float4* W4 = (const float4*)W;
    float4* Ws4 = (float4*)Ws;
#pragma unroll
    for (int i = 0; i < 5; i++) Ws4[tid + i * 128] = W4[tid + i * 128];

#pragma unroll
    for (int j = 0; j < 16; j++) {
        int i = tid + j * 128;
        int row = i >> 4, k4 = i & 15;
        float4 v = make_float4(0.f, 0.f, 0.f, 0.f);
        if (row < valid) v = ((const float4*)g_h1)[(size_t)(m0 + row) * 16 + k4];
        *(float4*)&Xs[row * 68 + k4 * 4] = v;
    }
    __syncthreads();

    int ty = tid >> 3, tx = tid & 7;
    int r0 = ty * 8, c0 = tx * 5;
    unsigned long long acc2[8][2];
    float acc1[8];
#pragma unroll
    for (int i = 0; i < 8; i++) {
        acc2[i][0] = pk2(0.f, 0.f);
        acc2[i][1] = pk2(0.f, 0.f);
        acc1[i] = 0.f;
    }

    for (int k = 0; k < 64; k += 4) {
        float4 a4[8];
#pragma unroll
        for (int i = 0; i < 8; i++) a4[i] = *(const float4*)&Xs[(r0 + i) * 68 + k];
#pragma unroll
        for (int kk = 0; kk < 4; kk++) {
            const float* brow = &Ws[(k + kk) * 40 + c0];
            unsigned long long bp0 = pk2(brow[0], brow[1]);
            unsigned long long bp1 = pk2(brow[2], brow[3]);
            float b4 = brow[4];
#pragma unroll
            for (int i = 0; i < 8; i++) {
                float av = ((const float*)&a4[i])[kk];
                unsigned long long av2 = pk2(av, av);
                fma2(acc2[i][0], av2, bp0);
                fma2(acc2[i][1], av2, bp1);
                acc1[i] = fmaf(av, b4, acc1[i]);
            }
        }
    }

    // Scalar __half stores only: c0 = tx*5 is odd for odd tx (no half2 alignment).
#pragma unroll
    for (int i = 0; i < 8; i++) {
        int row = m0 + r0 + i;
        if (row < NN) {
            float di = __ldg(&g_dinv[row]);
            float v0, v1, v2, v3;
            upk2(acc2[i][0], v0, v1);
            upk2(acc2[i][1], v2, v3);
            __half* dst = &g_h2[(size_t)row * 40 + c0];
            dst[0] = __float2half_rn(di * v0);
            dst[1] = __float2half_rn(di * v1);
            dst[2] = __float2half_rn(di * v2);
            dst[3] = __float2half_rn(di * v3);
            dst[4] = __float2half_rn(di * acc1[i]);
        }
    }
}

// ---------------- agg2: out = dinv[c]*(sum_r scaled[r] + scaled[c]) + b2 ----------------
// 5 lanes per node (6 nodes per warp, lanes 30,31 idle); each lane 8 fp16 ch (16B LDG.128).
__global__ void agg2_kernel(const float* __restrict__ b2, float* __restrict__ out) {
    int gtid = blockIdx.x * blockDim.x + threadIdx.x;
    int wid = gtid >> 5;
    int lane = gtid & 31;
    int g = lane / 5;
    int sub = lane - g * 5;
    if (g >= 6) return;
    int node = wid * 6 + g;
    if (node >= NN) return;
    const uint4* hh = (const uint4*)g_h2;  // 40 halves = 5 uint4 per row

    float acc[8];
    {
        uint4 sv = __ldg(&hh[(size_t)node * 5 + sub]);
        const __half2* hp = (const __half2*)&sv;
#pragma unroll
        for (int j = 0; j < 4; j++) {
            float2 f = __half22float2(hp[j]);
            acc[2 * j] = f.x;
            acc[2 * j + 1] = f.y;
        }
    }

    int s = node * ELLW;
    int e = s + __ldg(&g_cnt[node]);
    int k = s;
    for (; k + 4 <= e; k += 4) {
        int r0 = __ldg(&g_adj[k]);
        int r1 = __ldg(&g_adj[k + 1]);
        int r2 = __ldg(&g_adj[k + 2]);
        int r3 = __ldg(&g_adj[k + 3]);
        uint4 u0 = __ldg(&hh[(size_t)r0 * 5 + sub]);
        uint4 u1 = __ldg(&hh[(size_t)r1 * 5 + sub]);
        uint4 u2 = __ldg(&hh[(size_t)r2 * 5 + sub]);
        uint4 u3 = __ldg(&hh[(size_t)r3 * 5 + sub]);
        const __half2* p0 = (const __half2*)&u0;
        const __half2* p1 = (const __half2*)&u1;
        const __half2* p2 = (const __half2*)&u2;
        const __half2* p3 = (const __half2*)&u3;
#pragma unroll
        for (int j = 0; j < 4; j++) {
            float2 f0 = __half22float2(p0[j]);
            float2 f1 = __half22float2(p1[j]);
            float2 f2 = __half22float2(p2[j]);
            float2 f3 = __half22float2(p3[j]);
            acc[2 * j]     += (f0.x + f1.x) + (f2.x + f3.x);
            acc[2 * j + 1] += (f0.y + f1.y) + (f2.y + f3.y);
        }
    }
    for (; k < e; k++) {
        int r = __ldg(&g_adj[k]);
        uint4 u = __ldg(&hh[(size_t)r * 5 + sub]);
        const __half2* p = (const __half2*)&u;
#pragma unroll
        for (int j = 0; j < 4; j++) {
            float2 f = __half22float2(p[j]);
            acc[2 * j] += f.x;
            acc[2 * j + 1] += f.y;
        }
    }

    float di = __ldg(&g_dinv[node]);
    const float4* b24 = (const float4*)b2;
    float4 bb0 = __ldg(&b24[sub * 2]);
    float4 bb1 = __ldg(&b24[sub * 2 + 1]);
    float4 o0, o1;
    o0.x = fmaf(di, acc[0], bb0.x);
    o0.y = fmaf(di, acc[1], bb0.y);
    o0.z = fmaf(di, acc[2], bb0.z);
    o0.w = fmaf(di, acc[3], bb0.w);
    o1.x = fmaf(di, acc[4], bb1.x);
    o1.y = fmaf(di, acc[5], bb1.y);
    o1.z = fmaf(di, acc[6], bb1.z);
    o1.w = fmaf(di, acc[7], bb1.w);
    float4* dst = (float4*)&out[(size_t)node * 40 + sub * 8];
    dst[0] = o0;
    dst[1] = o1;
}

// ---------------- launch ----------------
extern "C" void kernel_launch(void* const* d_in, const int* in_sizes, int n_in,
                              void* d_out, int out_size) {
    const float* x  = (const float*)d_in[0];
    const void*  ei = d_in[1];
    const float* W1 = (const float*)d_in[2];
    const float* b1 = (const float*)d_in[3];
    const float* W2 = (const float*)d_in[4];
    const float* b2 = (const float*)d_in[5];
    float* out = (float*)d_out;

    init_kernel<<<(NN + 255) / 256, 256>>>(ei);
    scatter_ell_kernel<<<1024, 256>>>(ei);
    dinv_kernel<<<(NN + 255) / 256, 256>>>();

    cudaFuncSetAttribute(gemm1_kernel, cudaFuncAttributeMaxDynamicSharedMemorySize, G1_SMEM);
    gemm1_kernel<<<(NN + 127) / 128, 128, G1_SMEM>>>(x, W1);
    agg1_kernel<<<(NN * 8 + 255) / 256, 256>>>(b1);
    gemm2_kernel<<<(NN + 127) / 128, 128>>>(W2);
    agg2_kernel<<<(NN + 47) / 48, 256>>>(b2, out);
}